// round 2
// baseline (speedup 1.0000x reference)
#include <cuda_runtime.h>
#include <math.h>

// Problem constants
#define Bc 64
#define Nn 512
#define Lk 128
#define Mm 1024

#define MT 64        // columns (m) per CTA tile (after compaction)
#define NT 64        // rows (n) per chunk
#define NCHUNK (Nn / NT)
#define PX 132       // padded row stride of Xs (floats) -> conflict-free
#define PL 65        // padded row stride of Ls (floats)
#define THREADS 256

// Shared memory layout (in floats)
#define SM_WAS   0                   // [128][64] gathered Wa columns     (8192)
#define SM_XS    8192                // [64][PX]  X chunk                 (8448)
#define SM_LS    (8192 + 8448)       // [64][PL]  logits tile             (4160)
#define SM_SC    (SM_LS + 4160)      // [64]      s values for chunk
#define SM_RM    (SM_SC + 64)        // [64]      running max
#define SM_RD    (SM_RM + 64)        // [64]      running sum exp
#define SM_RT    (SM_RD + 64)        // [64]      running sum exp*s
#define SM_WS    (SM_RT + 64)        // [128]     Ws
#define SM_COLS  (SM_WS + 128)       // [64] int  gathered column indices
#define SMEM_FLOATS (SM_COLS + 64)
#define SMEM_BYTES (SMEM_FLOATS * 4)

// Scratch (device globals: no allocations allowed)
__device__ int g_list[Bc * Mm];
__device__ int g_cnt[Bc];

// ---------------------------------------------------------------------------
// Pre-kernel: per-batch compaction of active columns (K > 0) + zero inactive
// outputs. One CTA (1024 threads) per batch.
// ---------------------------------------------------------------------------
__global__ void __launch_bounds__(1024) compact_kernel(const int* __restrict__ K,
                                                       float* __restrict__ out) {
    int b = blockIdx.x;
    int m = threadIdx.x;
    int active = (K[b * Mm + m] > 0) ? 1 : 0;
    if (!active) out[b * Mm + m] = 0.0f;  // d_out poisoned 0xAA -> must zero

    __shared__ int wcnt[32];
    __shared__ int woff[32];

    unsigned bal = __ballot_sync(0xffffffffu, active);
    int lane = m & 31;
    int w = m >> 5;
    int pre = __popc(bal & ((1u << lane) - 1u));
    if (lane == 0) wcnt[w] = __popc(bal);
    __syncthreads();

    if (m < 32) {
        int v = wcnt[m];
#pragma unroll
        for (int d = 1; d < 32; d <<= 1) {
            int o = __shfl_up_sync(0xffffffffu, v, d);
            if (m >= d) v += o;
        }
        woff[m] = v - wcnt[m];  // exclusive prefix
        if (m == 31) g_cnt[b] = v;
    }
    __syncthreads();

    if (active) g_list[b * Mm + woff[w] + pre] = m;
}

// ---------------------------------------------------------------------------
// Main fused kernel: gathered-column logits GEMM + online softmax + weighted
// sum against s[b,n] = X[b,n,:].Ws, then sigmoid.
// Grid: (Mm/MT, Bc). CTAs whose tile is beyond the active count exit early.
// ---------------------------------------------------------------------------
__global__ void __launch_bounds__(THREADS, 2) fused_kernel(
    const float* __restrict__ X, const float* __restrict__ Wa,
    const float* __restrict__ Ws, const float* __restrict__ bs,
    float* __restrict__ out) {
    extern __shared__ float sm[];
    float* Was = sm + SM_WAS;
    float* Xs  = sm + SM_XS;
    float* Ls  = sm + SM_LS;
    float* sC  = sm + SM_SC;
    float* runM = sm + SM_RM;
    float* runD = sm + SM_RD;
    float* runT = sm + SM_RT;
    float* wss = sm + SM_WS;
    int*   cols = (int*)(sm + SM_COLS);

    const int b = blockIdx.y;
    const int t = threadIdx.x;

    const int A = g_cnt[b];
    const int j0 = blockIdx.x * MT;
    if (j0 >= A) return;                 // uniform across CTA
    const int Ac = min(MT, A - j0);

    // --- setup: column list, Ws, running stats ---
    if (t < MT) {
        int j = (t < Ac) ? (j0 + t) : j0;       // pad with col 0 (finite junk)
        cols[t] = g_list[b * Mm + j];
        runM[t] = -INFINITY;
        runD[t] = 0.0f;
        runT[t] = 0.0f;
    }
    if (t < Lk) wss[t] = Ws[t];
    __syncthreads();

    // --- gather Wa columns: Was[k][c] = Wa[k*M + cols[c]] ---
#pragma unroll
    for (int idx = t; idx < Lk * MT; idx += THREADS) {
        int k = idx >> 6;
        int c = idx & 63;
        Was[idx] = Wa[k * Mm + cols[c]];
    }

    const int ty = t >> 4;   // 0..15 -> rows ty*4..ty*4+3
    const int tx = t & 15;   // 0..15 -> cols tx*4..tx*4+3
    const float* xbase = &Xs[(ty * 4) * PX];
    const float* wbase = &Was[tx * 4];

    const float4* Xg = (const float4*)(X + ((size_t)b * Nn) * Lk);

    for (int chunk = 0; chunk < NCHUNK; ++chunk) {
        // --- load X chunk (coalesced float4, conflict-free STS) ---
        const int n0 = chunk * NT;
#pragma unroll
        for (int i = 0; i < 8; ++i) {
            int idx = t + THREADS * i;          // 0..2047 float4s
            int r = idx >> 5;                   // 0..63
            int c4 = idx & 31;                  // 0..31
            float4 v = Xg[(size_t)(n0 + r) * 32 + c4];
            *(float4*)&Xs[r * PX + c4 * 4] = v;
        }
        __syncthreads();

        // --- 64x64x128 fp32 register-tiled GEMM ---
        float acc[4][4];
#pragma unroll
        for (int i = 0; i < 4; ++i)
#pragma unroll
            for (int j = 0; j < 4; ++j) acc[i][j] = 0.0f;

#pragma unroll 8
        for (int k = 0; k < Lk; ++k) {
            float a0 = xbase[k];
            float a1 = xbase[PX + k];
            float a2 = xbase[2 * PX + k];
            float a3 = xbase[3 * PX + k];
            float4 bv = *(const float4*)&wbase[k * MT];
            acc[0][0] += a0 * bv.x; acc[0][1] += a0 * bv.y;
            acc[0][2] += a0 * bv.z; acc[0][3] += a0 * bv.w;
            acc[1][0] += a1 * bv.x; acc[1][1] += a1 * bv.y;
            acc[1][2] += a1 * bv.z; acc[1][3] += a1 * bv.w;
            acc[2][0] += a2 * bv.x; acc[2][1] += a2 * bv.y;
            acc[2][2] += a2 * bv.z; acc[2][3] += a2 * bv.w;
            acc[3][0] += a3 * bv.x; acc[3][1] += a3 * bv.y;
            acc[3][2] += a3 * bv.z; acc[3][3] += a3 * bv.w;
        }

        // --- s[n] = X[n,:].Ws for this chunk (4 threads per row) ---
        {
            int r = t >> 2, seg = t & 3;
            const float* xr = &Xs[r * PX + seg * 32];
            const float* wr = &wss[seg * 32];
            float a = 0.0f;
#pragma unroll
            for (int kk = 0; kk < 32; kk += 4) {
                float4 xv = *(const float4*)&xr[kk];
                float4 wv = *(const float4*)&wr[kk];
                a += xv.x * wv.x + xv.y * wv.y + xv.z * wv.z + xv.w * wv.w;
            }
            a += __shfl_xor_sync(0xffffffffu, a, 1);
            a += __shfl_xor_sync(0xffffffffu, a, 2);
            if (seg == 0) sC[r] = a;
        }

        // --- stage logits tile ---
#pragma unroll
        for (int i = 0; i < 4; ++i)
#pragma unroll
            for (int j = 0; j < 4; ++j)
                Ls[(ty * 4 + i) * PL + tx * 4 + j] = acc[i][j];
        __syncthreads();

        // --- online softmax update: 4 threads per column ---
        {
            int c = t >> 2, q = t & 3;
            const float* lcol = &Ls[(q * 16) * PL + c];
            float lm = -INFINITY;
#pragma unroll
            for (int rr = 0; rr < 16; ++rr) lm = fmaxf(lm, lcol[rr * PL]);
            lm = fmaxf(lm, __shfl_xor_sync(0xffffffffu, lm, 1));
            lm = fmaxf(lm, __shfl_xor_sync(0xffffffffu, lm, 2));

            float oldM = runM[c];
            float newM = fmaxf(oldM, lm);

            float le = 0.0f, lt = 0.0f;
#pragma unroll
            for (int rr = 0; rr < 16; ++rr) {
                float e = __expf(lcol[rr * PL] - newM);
                le += e;
                lt += e * sC[q * 16 + rr];
            }
            le += __shfl_xor_sync(0xffffffffu, le, 1);
            le += __shfl_xor_sync(0xffffffffu, le, 2);
            lt += __shfl_xor_sync(0xffffffffu, lt, 1);
            lt += __shfl_xor_sync(0xffffffffu, lt, 2);

            if (q == 0) {
                float corr = __expf(oldM - newM);   // 0 on first chunk
                runD[c] = runD[c] * corr + le;
                runT[c] = runT[c] * corr + lt;
                runM[c] = newM;
            }
        }
        __syncthreads();
    }

    // --- epilogue: sigmoid + scatter to original column indices ---
    if (t < Ac) {
        int m = cols[t];
        float v = runT[t] / runD[t] + bs[0];
        out[b * Mm + m] = 1.0f / (1.0f + __expf(-v));
    }
}

// ---------------------------------------------------------------------------
// Launch contract
// Inputs (metadata order): X f32[4194304], K i32[65536], Wa f32[131072],
//                          ba f32[1024] (dead), Ws f32[128], bs f32[1]
// Output: f32[65536]
// ---------------------------------------------------------------------------
extern "C" void kernel_launch(void* const* d_in, const int* in_sizes, int n_in,
                              void* d_out, int out_size) {
    const float* X  = (const float*)d_in[0];
    const int*   K  = (const int*)d_in[1];
    const float* Wa = (const float*)d_in[2];
    const float* Ws = (const float*)d_in[4];
    const float* bs = (const float*)d_in[5];
    float* out = (float*)d_out;

    cudaFuncSetAttribute(fused_kernel, cudaFuncAttributeMaxDynamicSharedMemorySize,
                         SMEM_BYTES);

    compact_kernel<<<Bc, 1024>>>(K, out);
    fused_kernel<<<dim3(Mm / MT, Bc), THREADS, SMEM_BYTES>>>(X, Wa, Ws, bs, out);
}

// round 3
// speedup vs baseline: 1.2939x; 1.2939x over previous
#include <cuda_runtime.h>
#include <math.h>

// Problem constants
#define Bc 64
#define Nn 512
#define Lk 128
#define Mm 1024

#define MT 64        // columns (m) per CTA tile (after compaction)
#define NT 128       // rows (n) per chunk
#define NCHUNK (Nn / NT)
#define THREADS 256

// Shared memory layout (in floats)
#define SM_WAS   0                         // [128][64] gathered Wa cols (32KB)
#define SM_XST   (Lk * MT)                 // [128][128] XT chunk, k-major (64KB)
#define SM_PMAX  SM_XST                    // overlay (XsT dead post-GEMM): [16][64]
#define SM_PSUM  (SM_XST + 1024)           // overlay [16][64]
#define SM_PTS   (SM_XST + 2048)           // overlay [16][64]
#define SM_SC    (SM_XST + Lk * NT)        // [128] s values for chunk
#define SM_RM    (SM_SC + NT)              // [64] running max
#define SM_RD    (SM_RM + MT)              // [64] running sum exp
#define SM_RT    (SM_RD + MT)              // [64] running sum exp*s
#define SM_NM    (SM_RT + MT)              // [64] new max (per chunk)
#define SM_COLS  (SM_NM + MT)              // [64] int gathered column indices
#define SMEM_FLOATS (SM_COLS + MT)
#define SMEM_BYTES (SMEM_FLOATS * 4)

typedef unsigned long long ull;

// Device scratch (no allocations allowed)
__device__ int   g_list[Bc * Mm];
__device__ int   g_cnt[Bc];
__device__ float g_XT[Bc * Lk * Nn];   // X transposed: [b][k][n]
__device__ float g_s[Bc * Nn];         // s[b][n] = X[b,n,:].Ws

// ---- packed f32x2 helpers -------------------------------------------------
__device__ __forceinline__ void ffma2(ull& d, ull a, ull b) {
    asm("fma.rn.f32x2 %0, %1, %2, %3;" : "=l"(d) : "l"(a), "l"(b), "l"(d));
}
__device__ __forceinline__ ull dup2(float x) {
    ull r;
    asm("mov.b64 %0, {%1, %1};" : "=l"(r) : "f"(x));
    return r;
}
__device__ __forceinline__ float lo2(ull a) { return __uint_as_float((unsigned)a); }
__device__ __forceinline__ float hi2(ull a) { return __uint_as_float((unsigned)(a >> 32)); }

// ---------------------------------------------------------------------------
// Pre-kernel 1: per-batch compaction of active columns (K > 0) + zero output.
// ---------------------------------------------------------------------------
__global__ void __launch_bounds__(1024) compact_kernel(const int* __restrict__ K,
                                                       float* __restrict__ out) {
    int b = blockIdx.x;
    int m = threadIdx.x;
    int active = (K[b * Mm + m] > 0) ? 1 : 0;
    if (!active) out[b * Mm + m] = 0.0f;

    __shared__ int wcnt[32];
    __shared__ int woff[32];

    unsigned bal = __ballot_sync(0xffffffffu, active);
    int lane = m & 31;
    int w = m >> 5;
    int pre = __popc(bal & ((1u << lane) - 1u));
    if (lane == 0) wcnt[w] = __popc(bal);
    __syncthreads();

    if (m < 32) {
        int v = wcnt[m];
#pragma unroll
        for (int d = 1; d < 32; d <<= 1) {
            int o = __shfl_up_sync(0xffffffffu, v, d);
            if (m >= d) v += o;
        }
        woff[m] = v - wcnt[m];
        if (m == 31) g_cnt[b] = v;
    }
    __syncthreads();

    if (active) g_list[b * Mm + woff[w] + pre] = m;
}

// ---------------------------------------------------------------------------
// Pre-kernel 2: tiled transpose X[b][n][k] -> g_XT[b][k][n].
// ---------------------------------------------------------------------------
__global__ void __launch_bounds__(256) transpose_kernel(const float* __restrict__ X) {
    __shared__ float tile[32][33];
    int k0 = blockIdx.x * 32;
    int n0 = blockIdx.y * 32;
    int b = blockIdx.z;
    int tx = threadIdx.x, ty = threadIdx.y;

    const float* Xb = X + (size_t)b * Nn * Lk;
    float* XTb = g_XT + (size_t)b * Lk * Nn;

#pragma unroll
    for (int j = 0; j < 32; j += 8)
        tile[ty + j][tx] = Xb[(size_t)(n0 + ty + j) * Lk + k0 + tx];
    __syncthreads();
#pragma unroll
    for (int j = 0; j < 32; j += 8)
        XTb[(size_t)(k0 + ty + j) * Nn + n0 + tx] = tile[tx][ty + j];
}

// ---------------------------------------------------------------------------
// Pre-kernel 3: g_s[b][n] = X[b,n,:].Ws  (one warp per 64 rows)
// ---------------------------------------------------------------------------
__global__ void __launch_bounds__(256) s_kernel(const float* __restrict__ X,
                                                const float* __restrict__ Ws) {
    int b = blockIdx.x;
    int w = threadIdx.x >> 5;
    int lane = threadIdx.x & 31;
    float4 wsv = ((const float4*)Ws)[lane];

    for (int n = w; n < Nn; n += 8) {
        float4 xv = ((const float4*)(X + ((size_t)b * Nn + n) * Lk))[lane];
        float d = xv.x * wsv.x + xv.y * wsv.y + xv.z * wsv.z + xv.w * wsv.w;
#pragma unroll
        for (int o = 16; o > 0; o >>= 1) d += __shfl_xor_sync(0xffffffffu, d, o);
        if (lane == 0) g_s[b * Nn + n] = d;
    }
}

// ---------------------------------------------------------------------------
// Main fused kernel: per-(batch, col-tile) logits GEMM (f32x2 packed) +
// register online softmax + weighted sum, then sigmoid.
// Thread map: ty = t>>4 owns 8 rows (as 4 f32x2 pairs), tx = t&15 owns 4 cols.
// ---------------------------------------------------------------------------
__global__ void __launch_bounds__(THREADS, 2) fused_kernel(
    const float* __restrict__ Wa, const float* __restrict__ bs,
    float* __restrict__ out) {
    extern __shared__ float sm[];
    float* Was  = sm + SM_WAS;
    float* XsT  = sm + SM_XST;
    float* pmax = sm + SM_PMAX;
    float* psum = sm + SM_PSUM;
    float* pts  = sm + SM_PTS;
    float* sC   = sm + SM_SC;
    float* runM = sm + SM_RM;
    float* runD = sm + SM_RD;
    float* runT = sm + SM_RT;
    float* newMs = sm + SM_NM;
    int*   cols = (int*)(sm + SM_COLS);

    const int b = blockIdx.y;
    const int t = threadIdx.x;

    const int A = g_cnt[b];
    const int j0 = blockIdx.x * MT;
    if (j0 >= A) return;
    const int Ac = min(MT, A - j0);

    if (t < MT) {
        int j = (t < Ac) ? (j0 + t) : j0;
        cols[t] = g_list[b * Mm + j];
        runM[t] = -INFINITY;
        runD[t] = 0.0f;
        runT[t] = 0.0f;
    }
    __syncthreads();

    // gather Wa columns: Was[k][c] = Wa[k*M + cols[c]]
#pragma unroll 4
    for (int idx = t; idx < Lk * MT; idx += THREADS) {
        int k = idx >> 6;
        int c = idx & 63;
        Was[idx] = Wa[k * Mm + cols[c]];
    }

    const int ty = t >> 4;          // 0..15 -> rows ty*8 .. ty*8+7
    const int tx = t & 15;          // 0..15 -> cols tx*4 .. tx*4+3
    const float* abase = &XsT[ty * 8];
    const float* bbase = &Was[tx * 4];

    const float4* XTg = (const float4*)(g_XT + (size_t)b * Lk * Nn);
    const float* sG = g_s + b * Nn;

    for (int chunk = 0; chunk < NCHUNK; ++chunk) {
        const int n0 = chunk * NT;

        // ---- load XT chunk: XsT[k][n-n0], coalesced float4, conflict-free ----
#pragma unroll
        for (int i = 0; i < 16; ++i) {
            int idx = t + THREADS * i;      // 0..4095 float4s
            int k = idx >> 5;               // 0..127
            int c4 = idx & 31;              // 0..31
            float4 v = XTg[k * (Nn / 4) + (n0 >> 2) + c4];
            *(float4*)&XsT[k * NT + c4 * 4] = v;
        }
        if (t < NT) sC[t] = sG[n0 + t];
        __syncthreads();

        // ---- 128x64x128 GEMM with packed f32x2 FFMA ----
        ull acc[4][4];
#pragma unroll
        for (int p = 0; p < 4; ++p)
#pragma unroll
            for (int c = 0; c < 4; ++c) acc[p][c] = 0ull;

#pragma unroll 4
        for (int k = 0; k < Lk; ++k) {
            ulonglong2 a01 = *(const ulonglong2*)&abase[k * NT];       // rows 0..3
            ulonglong2 a23 = *(const ulonglong2*)&abase[k * NT + 4];   // rows 4..7
            float4 bv = *(const float4*)&bbase[k * MT];
            ull b0 = dup2(bv.x), b1 = dup2(bv.y), b2 = dup2(bv.z), b3 = dup2(bv.w);
            ffma2(acc[0][0], a01.x, b0); ffma2(acc[0][1], a01.x, b1);
            ffma2(acc[0][2], a01.x, b2); ffma2(acc[0][3], a01.x, b3);
            ffma2(acc[1][0], a01.y, b0); ffma2(acc[1][1], a01.y, b1);
            ffma2(acc[1][2], a01.y, b2); ffma2(acc[1][3], a01.y, b3);
            ffma2(acc[2][0], a23.x, b0); ffma2(acc[2][1], a23.x, b1);
            ffma2(acc[2][2], a23.x, b2); ffma2(acc[2][3], a23.x, b3);
            ffma2(acc[3][0], a23.y, b0); ffma2(acc[3][1], a23.y, b1);
            ffma2(acc[3][2], a23.y, b2); ffma2(acc[3][3], a23.y, b3);
        }
        __syncthreads();   // all XsT reads done -> overlay region reusable

        // ---- register online softmax ----
        // 1) per-thread column maxima over 8 rows
        {
            float4 m4;
            float* m = (float*)&m4;
#pragma unroll
            for (int c = 0; c < 4; ++c) {
                float mm = -INFINITY;
#pragma unroll
                for (int p = 0; p < 4; ++p) {
                    mm = fmaxf(mm, lo2(acc[p][c]));
                    mm = fmaxf(mm, hi2(acc[p][c]));
                }
                m[c] = mm;
            }
            *(float4*)&pmax[ty * MT + tx * 4] = m4;
        }
        __syncthreads();

        // 2) reduce to chunk max, fold with running max
        if (t < MT) {
            float mm = -INFINITY;
#pragma unroll
            for (int i = 0; i < 16; ++i) mm = fmaxf(mm, pmax[i * MT + t]);
            newMs[t] = fmaxf(runM[t], mm);
        }
        __syncthreads();

        // 3) exp + per-thread partial sums
        {
            float nm[4];
#pragma unroll
            for (int c = 0; c < 4; ++c) nm[c] = newMs[tx * 4 + c];
            float sv[8];
#pragma unroll
            for (int r = 0; r < 8; ++r) sv[r] = sC[ty * 8 + r];

            float4 le4, lt4;
            float* le = (float*)&le4;
            float* lt = (float*)&lt4;
#pragma unroll
            for (int c = 0; c < 4; ++c) {
                float e = 0.0f, s = 0.0f;
#pragma unroll
                for (int p = 0; p < 4; ++p) {
                    float e0 = __expf(lo2(acc[p][c]) - nm[c]);
                    float e1 = __expf(hi2(acc[p][c]) - nm[c]);
                    e += e0 + e1;
                    s += e0 * sv[2 * p] + e1 * sv[2 * p + 1];
                }
                le[c] = e; lt[c] = s;
            }
            *(float4*)&psum[ty * MT + tx * 4] = le4;
            *(float4*)&pts[ty * MT + tx * 4]  = lt4;
        }
        __syncthreads();

        // 4) fold partials into running stats
        if (t < MT) {
            float se = 0.0f, st = 0.0f;
#pragma unroll
            for (int i = 0; i < 16; ++i) {
                se += psum[i * MT + t];
                st += pts[i * MT + t];
            }
            float corr = __expf(runM[t] - newMs[t]);   // 0 on first chunk
            runD[t] = runD[t] * corr + se;
            runT[t] = runT[t] * corr + st;
            runM[t] = newMs[t];
        }
        __syncthreads();
    }

    // ---- epilogue: sigmoid + scatter ----
    if (t < Ac) {
        int m = cols[t];
        float v = runT[t] / runD[t] + bs[0];
        out[b * Mm + m] = 1.0f / (1.0f + __expf(-v));
    }
}

// ---------------------------------------------------------------------------
// Launch contract
// Inputs: X f32[4194304], K i32[65536], Wa f32[131072], ba f32[1024] (dead),
//         Ws f32[128], bs f32[1].  Output: f32[65536]
// ---------------------------------------------------------------------------
extern "C" void kernel_launch(void* const* d_in, const int* in_sizes, int n_in,
                              void* d_out, int out_size) {
    const float* X  = (const float*)d_in[0];
    const int*   K  = (const int*)d_in[1];
    const float* Wa = (const float*)d_in[2];
    const float* Ws = (const float*)d_in[4];
    const float* bs = (const float*)d_in[5];
    float* out = (float*)d_out;

    cudaFuncSetAttribute(fused_kernel, cudaFuncAttributeMaxDynamicSharedMemorySize,
                         SMEM_BYTES);

    compact_kernel<<<Bc, 1024>>>(K, out);
    transpose_kernel<<<dim3(Lk / 32, Nn / 32, Bc), dim3(32, 8)>>>(X);
    s_kernel<<<Bc, 256>>>(X, Ws);
    fused_kernel<<<dim3(Mm / MT, Bc), THREADS, SMEM_BYTES>>>(Wa, bs, out);
}

// round 5
// speedup vs baseline: 2.2381x; 1.7297x over previous
#include <cuda_runtime.h>
#include <cuda_bf16.h>
#include <cstdint>
#include <math.h>

// Problem constants
#define Bc 64
#define Nn 512
#define Lk 128
#define Mm 1024

#define MT 64        // columns (m) per CTA tile (after compaction)
#define NT 128       // rows (n) per chunk
#define NCHUNK (Nn / NT)
#define THREADS 256

// Row stride for bf16 tiles: 136 halves = 272 bytes.
// 272 mod 128 = 16 -> 8 consecutive rows hit distinct 16B lanes:
// conflict-free ldmatrix and conflict-free STS.128 phases.
#define RSTRIDE_B 272

// ---- SMEM byte layout -----------------------------------------------------
#define SB_BHI  0                       // Was hi  [64 m][136 k]  17408B
#define SB_BLO  17408                   // Was lo                 17408B
#define SB_AHI  34816                   // X chunk hi [128 n][136 k] 34816B
#define SB_ALO  69632                   // X chunk lo             34816B
#define SB_SC   104448                  // s values [128] f32     512B
#define SB_COLS 104960                  // col indices [64] int   256B
#define SB_FOLD 105216                  // foldE[8][64], foldS[8][64] f32 4096B
#define SMEM_BYTES 109312

// ---- device scratch (no allocations allowed) ------------------------------
__device__ int   g_list[Bc * Mm];
__device__ int   g_cnt[Bc];
__device__ __nv_bfloat16 g_Xhi[Bc * Nn * Lk];
__device__ __nv_bfloat16 g_Xlo[Bc * Nn * Lk];
__device__ float g_s[Bc * Nn];

// ---- PTX helpers ----------------------------------------------------------
__device__ __forceinline__ uint32_t smem_u32(const void* p) {
    uint32_t a;
    asm("{ .reg .u64 t; cvta.to.shared.u64 t, %1; cvt.u32.u64 %0, t; }"
        : "=r"(a) : "l"(p));
    return a;
}
__device__ __forceinline__ void ldm4(uint32_t* r, uint32_t addr) {
    asm volatile("ldmatrix.sync.aligned.m8n8.x4.shared.b16 {%0,%1,%2,%3}, [%4];"
                 : "=r"(r[0]), "=r"(r[1]), "=r"(r[2]), "=r"(r[3]) : "r"(addr));
}
__device__ __forceinline__ void mma16816(float* c, const uint32_t* a,
                                         uint32_t b0, uint32_t b1) {
    asm volatile(
        "mma.sync.aligned.m16n8k16.row.col.f32.bf16.bf16.f32 "
        "{%0,%1,%2,%3}, {%4,%5,%6,%7}, {%8,%9}, {%0,%1,%2,%3};"
        : "+f"(c[0]), "+f"(c[1]), "+f"(c[2]), "+f"(c[3])
        : "r"(a[0]), "r"(a[1]), "r"(a[2]), "r"(a[3]), "r"(b0), "r"(b1));
}

// ---------------------------------------------------------------------------
// Pre-kernel 1: per-batch compaction of active columns (K > 0) + zero output.
// ---------------------------------------------------------------------------
__global__ void __launch_bounds__(1024) compact_kernel(const int* __restrict__ K,
                                                       float* __restrict__ out) {
    int b = blockIdx.x;
    int m = threadIdx.x;
    int active = (K[b * Mm + m] > 0) ? 1 : 0;
    if (!active) out[b * Mm + m] = 0.0f;

    __shared__ int wcnt[32];
    __shared__ int woff[32];

    unsigned bal = __ballot_sync(0xffffffffu, active);
    int lane = m & 31;
    int w = m >> 5;
    int pre = __popc(bal & ((1u << lane) - 1u));
    if (lane == 0) wcnt[w] = __popc(bal);
    __syncthreads();

    if (m < 32) {
        int v = wcnt[m];
#pragma unroll
        for (int d = 1; d < 32; d <<= 1) {
            int o = __shfl_up_sync(0xffffffffu, v, d);
            if (m >= d) v += o;
        }
        woff[m] = v - wcnt[m];
        if (m == 31) g_cnt[b] = v;
    }
    __syncthreads();

    if (active) g_list[b * Mm + woff[w] + pre] = m;
}

// ---------------------------------------------------------------------------
// Pre-kernel 2: X f32 -> bf16 hi/lo planes (same [b][n][k] layout).
// ---------------------------------------------------------------------------
__global__ void __launch_bounds__(256) convert_kernel(const float* __restrict__ X) {
    size_t i = (size_t)blockIdx.x * 256 + threadIdx.x;   // over 1,048,576 float4
    float4 v = ((const float4*)X)[i];
    float x[4] = {v.x, v.y, v.z, v.w};
    __nv_bfloat16 h[4], l[4];
#pragma unroll
    for (int j = 0; j < 4; ++j) {
        h[j] = __float2bfloat16_rn(x[j]);
        l[j] = __float2bfloat16_rn(x[j] - __bfloat162float(h[j]));
    }
    *(uint2*)&g_Xhi[i * 4] = *(uint2*)h;
    *(uint2*)&g_Xlo[i * 4] = *(uint2*)l;
}

// ---------------------------------------------------------------------------
// Pre-kernel 3: g_s[b][n] = X[b,n,:].Ws
// ---------------------------------------------------------------------------
__global__ void __launch_bounds__(256) s_kernel(const float* __restrict__ X,
                                                const float* __restrict__ Ws) {
    int b = blockIdx.x;
    int w = threadIdx.x >> 5;
    int lane = threadIdx.x & 31;
    float4 wsv = ((const float4*)Ws)[lane];

    for (int n = w; n < Nn; n += 8) {
        float4 xv = ((const float4*)(X + ((size_t)b * Nn + n) * Lk))[lane];
        float d = xv.x * wsv.x + xv.y * wsv.y + xv.z * wsv.z + xv.w * wsv.w;
#pragma unroll
        for (int o = 16; o > 0; o >>= 1) d += __shfl_xor_sync(0xffffffffu, d, o);
        if (lane == 0) g_s[b * Nn + n] = d;
    }
}

// ---------------------------------------------------------------------------
// Main fused kernel: mma.sync bf16-split logits GEMM + max-free register
// softmax sums. Grid (Mm/MT, Bc), 256 threads = 8 warps x 16 rows.
// ---------------------------------------------------------------------------
__global__ void __launch_bounds__(THREADS, 2) fused_kernel(
    const float* __restrict__ Wa, const float* __restrict__ bs,
    float* __restrict__ out) {
    extern __shared__ char smem[];
    const uint32_t sb = smem_u32(smem);
    const int t = threadIdx.x;
    const int wid = t >> 5;
    const int lane = t & 31;

    const int b = blockIdx.y;
    const int A = g_cnt[b];
    const int j0 = blockIdx.x * MT;
    if (j0 >= A) return;
    const int Ac = min(MT, A - j0);

    int* cols = (int*)(smem + SB_COLS);
    float* sC = (float*)(smem + SB_SC);
    __nv_bfloat16* BHIp = (__nv_bfloat16*)(smem + SB_BHI);
    __nv_bfloat16* BLOp = (__nv_bfloat16*)(smem + SB_BLO);

    if (t < MT) {
        int j = (t < Ac) ? (j0 + t) : j0;
        cols[t] = g_list[b * Mm + j];
    }
    __syncthreads();

    // ---- gather + split Wa columns: Was[m][k], stride 136 halves ----
#pragma unroll 4
    for (int i = 0; i < 32; ++i) {
        int idx = t + THREADS * i;        // 0..8191
        int k = idx >> 6;                 // 0..127
        int m = idx & 63;                 // 0..63
        float x = Wa[k * Mm + cols[m]];
        __nv_bfloat16 h = __float2bfloat16_rn(x);
        __nv_bfloat16 l = __float2bfloat16_rn(x - __bfloat162float(h));
        int off = m * 136 + k;
        BHIp[off] = h;
        BLOp[off] = l;
    }

    const char* Xhi = (const char*)(g_Xhi + (size_t)b * Nn * Lk);
    const char* Xlo = (const char*)(g_Xlo + (size_t)b * Nn * Lk);
    const float* sG = g_s + b * Nn;

    const int rowbase = wid * 16;

    // A-ldmatrix lane address components (x4: 4 groups of 8 lanes)
    const int a_row = rowbase + (lane & 7) + ((lane >> 3) & 1) * 8;
    const int a_cb  = (lane >> 4) * 16;       // +16B for k-high mats
    // B-ldmatrix lane address components
    const int b_rowoff = (lane & 7) + (lane >> 4) * 8;   // + np*16
    const int b_cb  = ((lane >> 3) & 1) * 16;

    // persistent softmax sums: [ntile][col j]
    float sumE[8][2], sumES[8][2];
#pragma unroll
    for (int nt = 0; nt < 8; ++nt) {
        sumE[nt][0] = sumE[nt][1] = 0.0f;
        sumES[nt][0] = sumES[nt][1] = 0.0f;
    }

    for (int chunk = 0; chunk < NCHUNK; ++chunk) {
        const int n0 = chunk * NT;
        if (chunk) __syncthreads();    // prior chunk's A/sC reads done

        // ---- stage X chunk hi/lo: [n][k] stride 272B, coalesced 16B ----
#pragma unroll
        for (int i = 0; i < 8; ++i) {
            int idx = t + THREADS * i;  // 0..2047 16B-groups
            int n = idx >> 4;           // 0..127
            int g = idx & 15;           // 0..15
            size_t gsrc = ((size_t)(n0 + n) * Lk + g * 8) * 2;
            *(uint4*)(smem + SB_AHI + n * RSTRIDE_B + g * 16) =
                *(const uint4*)(Xhi + gsrc);
            *(uint4*)(smem + SB_ALO + n * RSTRIDE_B + g * 16) =
                *(const uint4*)(Xlo + gsrc);
        }
        if (t < NT) sC[t] = sG[n0 + t];
        __syncthreads();               // also covers the one-time Wa gather

        // ---- GEMM: 16x64x128 per warp, 3-pass bf16 split ----
        float acc[8][4];
#pragma unroll
        for (int nt = 0; nt < 8; ++nt)
#pragma unroll
            for (int j = 0; j < 4; ++j) acc[nt][j] = 0.0f;

#pragma unroll
        for (int kt = 0; kt < 8; ++kt) {
            uint32_t ah[4], al[4];
            uint32_t aaddr = sb + SB_AHI + a_row * RSTRIDE_B + kt * 32 + a_cb;
            ldm4(ah, aaddr);
            ldm4(al, aaddr + (SB_ALO - SB_AHI));
#pragma unroll
            for (int np = 0; np < 4; ++np) {
                uint32_t bh[4], bl[4];
                uint32_t baddr = sb + SB_BHI + (np * 16 + b_rowoff) * RSTRIDE_B
                               + kt * 32 + b_cb;
                ldm4(bh, baddr);
                ldm4(bl, baddr + (SB_BLO - SB_BHI));
                mma16816(acc[2 * np],     ah, bh[0], bh[1]);
                mma16816(acc[2 * np],     ah, bl[0], bl[1]);
                mma16816(acc[2 * np],     al, bh[0], bh[1]);
                mma16816(acc[2 * np + 1], ah, bh[2], bh[3]);
                mma16816(acc[2 * np + 1], ah, bl[2], bl[3]);
                mma16816(acc[2 * np + 1], al, bh[2], bh[3]);
            }
        }

        // ---- epilogue (registers only): exp + weighted accumulate ----
        {
            float s0 = sC[rowbase + (lane >> 2)];
            float s1 = sC[rowbase + 8 + (lane >> 2)];
#pragma unroll
            for (int nt = 0; nt < 8; ++nt) {
                float e0 = __expf(acc[nt][0]);
                float e1 = __expf(acc[nt][1]);
                float e2 = __expf(acc[nt][2]);
                float e3 = __expf(acc[nt][3]);
                sumE[nt][0] += e0 + e2;
                sumE[nt][1] += e1 + e3;
                sumES[nt][0] += e0 * s0 + e2 * s1;
                sumES[nt][1] += e1 * s0 + e3 * s1;
            }
        }
    }

    // ---- cross-lane fold over the 8 row-groups of the warp ----
#pragma unroll
    for (int nt = 0; nt < 8; ++nt)
#pragma unroll
        for (int j = 0; j < 2; ++j) {
            float e = sumE[nt][j], s = sumES[nt][j];
            e += __shfl_xor_sync(0xffffffffu, e, 4);
            e += __shfl_xor_sync(0xffffffffu, e, 8);
            e += __shfl_xor_sync(0xffffffffu, e, 16);
            s += __shfl_xor_sync(0xffffffffu, s, 4);
            s += __shfl_xor_sync(0xffffffffu, s, 8);
            s += __shfl_xor_sync(0xffffffffu, s, 16);
            sumE[nt][j] = e;
            sumES[nt][j] = s;
        }

    float* foldE = (float*)(smem + SB_FOLD);
    float* foldS = foldE + 512;
    if (lane < 4) {
#pragma unroll
        for (int nt = 0; nt < 8; ++nt)
#pragma unroll
            for (int j = 0; j < 2; ++j) {
                int c = nt * 8 + lane * 2 + j;
                foldE[wid * 64 + c] = sumE[nt][j];
                foldS[wid * 64 + c] = sumES[nt][j];
            }
    }
    __syncthreads();

    // ---- fold 8 warps, sigmoid, scatter ----
    if (t < Ac) {
        float se = 0.0f, st = 0.0f;
#pragma unroll
        for (int w = 0; w < 8; ++w) {
            se += foldE[w * 64 + t];
            st += foldS[w * 64 + t];
        }
        float v = st / se + bs[0];
        out[b * Mm + cols[t]] = 1.0f / (1.0f + __expf(-v));
    }
}

// ---------------------------------------------------------------------------
// Launch contract
// Inputs: X f32[4194304], K i32[65536], Wa f32[131072], ba f32[1024] (dead),
//         Ws f32[128], bs f32[1].  Output: f32[65536]
// ---------------------------------------------------------------------------
extern "C" void kernel_launch(void* const* d_in, const int* in_sizes, int n_in,
                              void* d_out, int out_size) {
    const float* X  = (const float*)d_in[0];
    const int*   K  = (const int*)d_in[1];
    const float* Wa = (const float*)d_in[2];
    const float* Ws = (const float*)d_in[4];
    const float* bs = (const float*)d_in[5];
    float* out = (float*)d_out;

    cudaFuncSetAttribute(fused_kernel, cudaFuncAttributeMaxDynamicSharedMemorySize,
                         SMEM_BYTES);

    compact_kernel<<<Bc, 1024>>>(K, out);
    convert_kernel<<<(Bc * Nn * Lk / 4) / 256, 256>>>(X);
    s_kernel<<<Bc, 256>>>(X, Ws);
    fused_kernel<<<dim3(Mm / MT, Bc), THREADS, SMEM_BYTES>>>(Wa, bs, out);
}

// round 6
// speedup vs baseline: 3.2568x; 1.4552x over previous
#include <cuda_runtime.h>
#include <cuda_fp16.h>
#include <cstdint>
#include <math.h>

// Problem constants
#define Bc 64
#define Nn 512
#define Lk 128
#define Mm 1024

#define MT 64        // columns (m) per CTA tile (after compaction)
#define NT 128       // rows (n) per chunk
#define NCHUNK (Nn / NT)
#define THREADS 256

// Row stride for fp16 tiles: 136 halves = 272 bytes.
// 272 mod 128 = 16 -> consecutive rows hit distinct 16B lanes:
// conflict-free ldmatrix and conflict-free STS phases.
#define RSTRIDE_B 272

// ---- SMEM byte layout -----------------------------------------------------
#define SB_B    0                       // Was fp16 [64 m][136 k]   17408B
#define SB_A    17408                   // X chunk fp16 [128][136]  34816B
#define SB_SC   52224                   // s values [128] f32       512B
#define SB_COLS 52736                   // col indices [64] int     256B
#define SB_FOLD 52992                   // foldE[4][64], foldS[4][64] 2048B
#define SMEM_BYTES 55040

// ---- device scratch (no allocations allowed) ------------------------------
__device__ int   g_list[Bc * Mm];
__device__ int   g_cnt[Bc];
__device__ float g_s[Bc * Nn];

// ---- PTX helpers ----------------------------------------------------------
__device__ __forceinline__ uint32_t smem_u32(const void* p) {
    uint32_t a;
    asm("{ .reg .u64 t; cvta.to.shared.u64 t, %1; cvt.u32.u64 %0, t; }"
        : "=r"(a) : "l"(p));
    return a;
}
__device__ __forceinline__ void ldm4(uint32_t* r, uint32_t addr) {
    asm volatile("ldmatrix.sync.aligned.m8n8.x4.shared.b16 {%0,%1,%2,%3}, [%4];"
                 : "=r"(r[0]), "=r"(r[1]), "=r"(r[2]), "=r"(r[3]) : "r"(addr));
}
__device__ __forceinline__ void mma16816(float* c, const uint32_t* a,
                                         uint32_t b0, uint32_t b1) {
    asm volatile(
        "mma.sync.aligned.m16n8k16.row.col.f32.f16.f16.f32 "
        "{%0,%1,%2,%3}, {%4,%5,%6,%7}, {%8,%9}, {%0,%1,%2,%3};"
        : "+f"(c[0]), "+f"(c[1]), "+f"(c[2]), "+f"(c[3])
        : "r"(a[0]), "r"(a[1]), "r"(a[2]), "r"(a[3]), "r"(b0), "r"(b1));
}

// ---------------------------------------------------------------------------
// Pre-kernel 1: per-batch compaction of active columns (K > 0) + zero output.
// ---------------------------------------------------------------------------
__global__ void __launch_bounds__(1024) compact_kernel(const int* __restrict__ K,
                                                       float* __restrict__ out) {
    int b = blockIdx.x;
    int m = threadIdx.x;
    int active = (K[b * Mm + m] > 0) ? 1 : 0;
    if (!active) out[b * Mm + m] = 0.0f;

    __shared__ int wcnt[32];
    __shared__ int woff[32];

    unsigned bal = __ballot_sync(0xffffffffu, active);
    int lane = m & 31;
    int w = m >> 5;
    int pre = __popc(bal & ((1u << lane) - 1u));
    if (lane == 0) wcnt[w] = __popc(bal);
    __syncthreads();

    if (m < 32) {
        int v = wcnt[m];
#pragma unroll
        for (int d = 1; d < 32; d <<= 1) {
            int o = __shfl_up_sync(0xffffffffu, v, d);
            if (m >= d) v += o;
        }
        woff[m] = v - wcnt[m];
        if (m == 31) g_cnt[b] = v;
    }
    __syncthreads();

    if (active) g_list[b * Mm + woff[w] + pre] = m;
}

// ---------------------------------------------------------------------------
// Pre-kernel 2: g_s[b][n] = X[b,n,:].Ws
// ---------------------------------------------------------------------------
__global__ void __launch_bounds__(256) s_kernel(const float* __restrict__ X,
                                                const float* __restrict__ Ws) {
    int b = blockIdx.x;
    int w = threadIdx.x >> 5;
    int lane = threadIdx.x & 31;
    float4 wsv = ((const float4*)Ws)[lane];

    for (int n = w; n < Nn; n += 8) {
        float4 xv = ((const float4*)(X + ((size_t)b * Nn + n) * Lk))[lane];
        float d = xv.x * wsv.x + xv.y * wsv.y + xv.z * wsv.z + xv.w * wsv.w;
#pragma unroll
        for (int o = 16; o > 0; o >>= 1) d += __shfl_xor_sync(0xffffffffu, d, o);
        if (lane == 0) g_s[b * Nn + n] = d;
    }
}

// ---------------------------------------------------------------------------
// Main fused kernel: single-pass fp16 mma.sync logits GEMM + max-free
// register softmax sums. Grid (Mm/MT, Bc), 256 threads = 8 warps.
// Warp map: wr = wid&3 owns rows wr*32..+31, wc = wid>>2 owns cols wc*32..+31.
// ---------------------------------------------------------------------------
__global__ void __launch_bounds__(THREADS, 3) fused_kernel(
    const float* __restrict__ X, const float* __restrict__ Wa,
    const float* __restrict__ bs, float* __restrict__ out) {
    extern __shared__ char smem[];
    const uint32_t sb = smem_u32(smem);
    const int t = threadIdx.x;
    const int wid = t >> 5;
    const int lane = t & 31;
    const int wr = wid & 3;
    const int wc = wid >> 2;

    const int b = blockIdx.y;
    const int A = g_cnt[b];
    const int j0 = blockIdx.x * MT;
    if (j0 >= A) return;
    const int Ac = min(MT, A - j0);

    int* cols = (int*)(smem + SB_COLS);
    float* sC = (float*)(smem + SB_SC);
    __half* Bp = (__half*)(smem + SB_B);

    if (t < MT) {
        int j = (t < Ac) ? (j0 + t) : j0;
        cols[t] = g_list[b * Mm + j];
    }
    __syncthreads();

    // ---- gather + convert Wa columns to fp16: Was[m][k], stride 136 ----
#pragma unroll 4
    for (int i = 0; i < 32; ++i) {
        int idx = t + THREADS * i;        // 0..8191
        int k = idx >> 6;                 // 0..127
        int m = idx & 63;                 // 0..63
        Bp[m * 136 + k] = __float2half_rn(Wa[k * Mm + cols[m]]);
    }

    const float* Xb = X + (size_t)b * Nn * Lk;
    const float* sG = g_s + b * Nn;

    // ldmatrix lane address components
    const int a_row8 = (lane & 7) + ((lane >> 3) & 1) * 8;  // + wr*32 + mt*16
    const int a_cb   = (lane >> 4) * 16;                    // + kt*32
    const int b_row8 = (lane & 7) + (lane >> 4) * 8;        // + wc*32 + np*16
    const int b_cb   = ((lane >> 3) & 1) * 16;              // + kt*32

    // persistent softmax sums over n: [ntile 0..3][col j 0..1]
    float sumE[4][2], sumES[4][2];
#pragma unroll
    for (int nt = 0; nt < 4; ++nt) {
        sumE[nt][0] = sumE[nt][1] = 0.0f;
        sumES[nt][0] = sumES[nt][1] = 0.0f;
    }

    for (int chunk = 0; chunk < NCHUNK; ++chunk) {
        const int n0 = chunk * NT;
        if (chunk) __syncthreads();    // prior chunk's A/sC reads done

        // ---- stage X chunk -> fp16: [n][k] stride 272B, coalesced ----
#pragma unroll
        for (int i = 0; i < 16; ++i) {
            int idx = t + THREADS * i;  // 0..4095 8B-granules
            int n = idx >> 5;           // 0..127
            int g = idx & 31;           // 0..31
            float4 v = *(const float4*)(Xb + (size_t)(n0 + n) * Lk + g * 4);
            __half2 h0 = __float22half2_rn(make_float2(v.x, v.y));
            __half2 h1 = __float22half2_rn(make_float2(v.z, v.w));
            uint2 pk = make_uint2(*(uint32_t*)&h0, *(uint32_t*)&h1);
            *(uint2*)(smem + SB_A + n * RSTRIDE_B + g * 8) = pk;
        }
        if (t < NT) sC[t] = sG[n0 + t];
        __syncthreads();               // also covers the one-time Wa gather

        // ---- GEMM: 32x32x128 per warp, single-pass fp16 ----
        float acc[2][4][4];
#pragma unroll
        for (int mt = 0; mt < 2; ++mt)
#pragma unroll
            for (int nt = 0; nt < 4; ++nt)
#pragma unroll
                for (int j = 0; j < 4; ++j) acc[mt][nt][j] = 0.0f;

#pragma unroll
        for (int kt = 0; kt < 8; ++kt) {
            uint32_t af[2][4];
#pragma unroll
            for (int mt = 0; mt < 2; ++mt) {
                int row = wr * 32 + mt * 16 + a_row8;
                ldm4(af[mt], sb + SB_A + row * RSTRIDE_B + kt * 32 + a_cb);
            }
#pragma unroll
            for (int np = 0; np < 2; ++np) {
                uint32_t bf[4];
                int m = wc * 32 + np * 16 + b_row8;
                ldm4(bf, sb + SB_B + m * RSTRIDE_B + kt * 32 + b_cb);
#pragma unroll
                for (int mt = 0; mt < 2; ++mt) {
                    mma16816(acc[mt][2 * np],     af[mt], bf[0], bf[1]);
                    mma16816(acc[mt][2 * np + 1], af[mt], bf[2], bf[3]);
                }
            }
        }

        // ---- epilogue (registers only): exp + weighted accumulate ----
#pragma unroll
        for (int mt = 0; mt < 2; ++mt) {
            float s0 = sC[wr * 32 + mt * 16 + (lane >> 2)];
            float s1 = sC[wr * 32 + mt * 16 + 8 + (lane >> 2)];
#pragma unroll
            for (int nt = 0; nt < 4; ++nt) {
                float e0 = __expf(acc[mt][nt][0]);
                float e1 = __expf(acc[mt][nt][1]);
                float e2 = __expf(acc[mt][nt][2]);
                float e3 = __expf(acc[mt][nt][3]);
                sumE[nt][0] += e0 + e2;
                sumE[nt][1] += e1 + e3;
                sumES[nt][0] += e0 * s0 + e2 * s1;
                sumES[nt][1] += e1 * s0 + e3 * s1;
            }
        }
    }

    // ---- cross-lane fold (rows within warp live on lane bits 2..4) ----
#pragma unroll
    for (int nt = 0; nt < 4; ++nt)
#pragma unroll
        for (int j = 0; j < 2; ++j) {
            float e = sumE[nt][j], s = sumES[nt][j];
            e += __shfl_xor_sync(0xffffffffu, e, 4);
            e += __shfl_xor_sync(0xffffffffu, e, 8);
            e += __shfl_xor_sync(0xffffffffu, e, 16);
            s += __shfl_xor_sync(0xffffffffu, s, 4);
            s += __shfl_xor_sync(0xffffffffu, s, 8);
            s += __shfl_xor_sync(0xffffffffu, s, 16);
            sumE[nt][j] = e;
            sumES[nt][j] = s;
        }

    float* foldE = (float*)(smem + SB_FOLD);
    float* foldS = foldE + 256;
    if (lane < 4) {
#pragma unroll
        for (int nt = 0; nt < 4; ++nt)
#pragma unroll
            for (int j = 0; j < 2; ++j) {
                int c = wc * 32 + nt * 8 + lane * 2 + j;
                foldE[wr * 64 + c] = sumE[nt][j];
                foldS[wr * 64 + c] = sumES[nt][j];
            }
    }
    __syncthreads();

    // ---- fold 4 row-groups, sigmoid, scatter ----
    if (t < Ac) {
        float se = foldE[t] + foldE[64 + t] + foldE[128 + t] + foldE[192 + t];
        float st = foldS[t] + foldS[64 + t] + foldS[128 + t] + foldS[192 + t];
        float v = st / se + bs[0];
        out[b * Mm + cols[t]] = 1.0f / (1.0f + __expf(-v));
    }
}

// ---------------------------------------------------------------------------
// Launch contract
// Inputs: X f32[4194304], K i32[65536], Wa f32[131072], ba f32[1024] (dead),
//         Ws f32[128], bs f32[1].  Output: f32[65536]
// ---------------------------------------------------------------------------
extern "C" void kernel_launch(void* const* d_in, const int* in_sizes, int n_in,
                              void* d_out, int out_size) {
    const float* X  = (const float*)d_in[0];
    const int*   K  = (const int*)d_in[1];
    const float* Wa = (const float*)d_in[2];
    const float* Ws = (const float*)d_in[4];
    const float* bs = (const float*)d_in[5];
    float* out = (float*)d_out;

    cudaFuncSetAttribute(fused_kernel, cudaFuncAttributeMaxDynamicSharedMemorySize,
                         SMEM_BYTES);

    compact_kernel<<<Bc, 1024>>>(K, out);
    s_kernel<<<Bc, 256>>>(X, Ws);
    fused_kernel<<<dim3(Mm / MT, Bc), THREADS, SMEM_BYTES>>>(X, Wa, bs, out);
}